// round 2
// baseline (speedup 1.0000x reference)
#include <cuda_runtime.h>
#include <math.h>

#define BATCH 2
#define SEQ   4096
#define DM    1024
#define DIP   4256
#define DI    2048
#define CDIM  2176
#define NH    32
#define HD    64
#define NSTATE 64
#define M_ROWS (BATCH*SEQ)   /* 8192 */

// ---------------- scratch (device globals; no allocations allowed) ----------------
__device__ float g_ln[(size_t)M_ROWS * DM];
__device__ float g_zx[(size_t)M_ROWS * DIP];
__device__ float g_conv[(size_t)M_ROWS * CDIM];
__device__ float g_dt[(size_t)M_ROWS * NH];
__device__ float g_dA[(size_t)M_ROWS * NH];
__device__ float g_y[(size_t)M_ROWS * DI];
__device__ float g_h[(size_t)M_ROWS * DM];

// ---------------- LayerNorm: one block per row of 1024 ----------------
__global__ void ln_kernel(const float* __restrict__ x, const float* __restrict__ w,
                          const float* __restrict__ b, float* __restrict__ out)
{
    __shared__ float sh1[8], sh2[8];
    const int row = blockIdx.x;
    const int tid = threadIdx.x;
    const float4 v = ((const float4*)(x + (size_t)row * DM))[tid];
    float s1 = v.x + v.y + v.z + v.w;
    float s2 = v.x*v.x + v.y*v.y + v.z*v.z + v.w*v.w;
#pragma unroll
    for (int o = 16; o; o >>= 1) {
        s1 += __shfl_xor_sync(0xffffffffu, s1, o);
        s2 += __shfl_xor_sync(0xffffffffu, s2, o);
    }
    if ((tid & 31) == 0) { sh1[tid >> 5] = s1; sh2[tid >> 5] = s2; }
    __syncthreads();
    if (tid < 32) {
        s1 = (tid < 8) ? sh1[tid] : 0.f;
        s2 = (tid < 8) ? sh2[tid] : 0.f;
#pragma unroll
        for (int o = 4; o; o >>= 1) {
            s1 += __shfl_xor_sync(0xffffffffu, s1, o);
            s2 += __shfl_xor_sync(0xffffffffu, s2, o);
        }
        if (tid == 0) { sh1[0] = s1; sh2[0] = s2; }
    }
    __syncthreads();
    const float mean = sh1[0] * (1.f / DM);
    const float var  = sh2[0] * (1.f / DM) - mean * mean;
    const float rstd = rsqrtf(var + 1e-5f);
    const float4 wv = ((const float4*)w)[tid];
    const float4 bv = ((const float4*)b)[tid];
    float4 o;
    o.x = (v.x - mean) * rstd * wv.x + bv.x;
    o.y = (v.y - mean) * rstd * wv.y + bv.y;
    o.z = (v.z - mean) * rstd * wv.z + bv.z;
    o.w = (v.w - mean) * rstd * wv.w + bv.w;
    ((float4*)(out + (size_t)row * DM))[tid] = o;
}

// ---------------- NT GEMM: C[M,N] = A[M,K] * B[N,K]^T (+Res) ----------------
// 128x128 tile, BK=8, 256 threads, 8x8 per thread (split 4+4 microtile)
__global__ __launch_bounds__(256, 2)
void gemm_nt(const float* __restrict__ A, const float* __restrict__ Bw,
             const float* __restrict__ Res, float* __restrict__ C,
             int M, int N, int K)
{
    __shared__ float As[8][128];
    __shared__ float Bs[8][128];
    const int tid = threadIdx.x;
    const int bm = blockIdx.y * 128;
    const int bn = blockIdx.x * 128;
    const int tx = tid & 15;
    const int ty = tid >> 4;
    const int lr = tid >> 1;          // 0..127 row within tile
    const int lk = (tid & 1) * 4;     // 0 or 4

    float acc[8][8];
#pragma unroll
    for (int i = 0; i < 8; i++)
#pragma unroll
        for (int j = 0; j < 8; j++) acc[i][j] = 0.f;

    const float* Ap = A + (size_t)(bm + lr) * K + lk;
    const bool  bok = (bn + lr) < N;
    const float* Bp = Bw + (size_t)(bok ? (bn + lr) : 0) * K + lk;

    for (int k0 = 0; k0 < K; k0 += 8) {
        const float4 av = *(const float4*)(Ap + k0);
        float4 bv = make_float4(0.f, 0.f, 0.f, 0.f);
        if (bok) bv = *(const float4*)(Bp + k0);
        As[lk+0][lr] = av.x; As[lk+1][lr] = av.y; As[lk+2][lr] = av.z; As[lk+3][lr] = av.w;
        Bs[lk+0][lr] = bv.x; Bs[lk+1][lr] = bv.y; Bs[lk+2][lr] = bv.z; Bs[lk+3][lr] = bv.w;
        __syncthreads();
#pragma unroll
        for (int kk = 0; kk < 8; kk++) {
            float a[8], b[8];
            *(float4*)(a + 0) = *(const float4*)&As[kk][ty * 4];
            *(float4*)(a + 4) = *(const float4*)&As[kk][64 + ty * 4];
            *(float4*)(b + 0) = *(const float4*)&Bs[kk][tx * 4];
            *(float4*)(b + 4) = *(const float4*)&Bs[kk][64 + tx * 4];
#pragma unroll
            for (int i = 0; i < 8; i++)
#pragma unroll
                for (int j = 0; j < 8; j++)
                    acc[i][j] = fmaf(a[i], b[j], acc[i][j]);
        }
        __syncthreads();
    }

#pragma unroll
    for (int ih = 0; ih < 2; ih++)
#pragma unroll
    for (int i = 0; i < 4; i++) {
        const int m = bm + ih * 64 + ty * 4 + i;
#pragma unroll
        for (int jh = 0; jh < 2; jh++) {
            const int n = bn + jh * 64 + tx * 4;
            if (n < N) {
                float4 v;
                v.x = acc[ih*4+i][jh*4+0];
                v.y = acc[ih*4+i][jh*4+1];
                v.z = acc[ih*4+i][jh*4+2];
                v.w = acc[ih*4+i][jh*4+3];
                if (Res) {
                    const float4 r = *(const float4*)&Res[(size_t)m * N + n];
                    v.x += r.x; v.y += r.y; v.z += r.z; v.w += r.w;
                }
                *(float4*)&C[(size_t)m * N + n] = v;
            }
        }
    }
}

// ---------------- dt/softplus/dA ----------------
__global__ void dt_kernel(const float* __restrict__ dt_bias, const float* __restrict__ A_log)
{
    const int idx = blockIdx.x * blockDim.x + threadIdx.x;  // < M_ROWS*NH
    const int h = idx & (NH - 1);
    const int row = idx >> 5;
    const float raw = g_zx[(size_t)row * DIP + (DI + CDIM) + h] + dt_bias[h];
    const float dt = (raw > 20.f) ? raw : log1pf(expf(raw));
    const float A = -expf(A_log[h]);
    g_dt[idx] = dt;
    g_dA[idx] = expf(dt * A);
}

// ---------------- causal depthwise conv (d=4) + bias + SiLU ----------------
__global__ void conv_kernel(const float* __restrict__ cw, const float* __restrict__ cb)
{
    const int idx = blockIdx.x * blockDim.x + threadIdx.x;
    if (idx >= M_ROWS * CDIM) return;
    const int c = idx % CDIM;
    const int row = idx / CDIM;
    const int l = row & (SEQ - 1);
    const float w0 = cw[c*4+0], w1 = cw[c*4+1], w2 = cw[c*4+2], w3 = cw[c*4+3];
    float acc = cb[c];
    const size_t base = (size_t)row * DIP + DI + c;
    acc += g_zx[base] * w3;
    if (l >= 1) acc += g_zx[base - (size_t)DIP]     * w2;
    if (l >= 2) acc += g_zx[base - 2*(size_t)DIP]   * w1;
    if (l >= 3) acc += g_zx[base - 3*(size_t)DIP]   * w0;
    g_conv[idx] = acc * (1.f / (1.f + expf(-acc)));
}

// ---------------- sequential selective scan: one CTA per (b,h) ----------------
// 256 threads: thread (p = tid>>2, g = tid&3) owns state[p][g*16 : g*16+16]
__global__ __launch_bounds__(256, 1)
void scan_kernel(const float* __restrict__ Dp)
{
    const int bh = blockIdx.x;
    const int b = bh >> 5, h = bh & 31;
    const int tid = threadIdx.x;
    const int p = tid >> 2, g = tid & 3, nb = g * 16;

    __shared__ float sX[16][64], sB[16][64], sC[16][64], sY[16][64];
    __shared__ float sdt[16], sda[16];

    float st[16];
#pragma unroll
    for (int i = 0; i < 16; i++) st[i] = 0.f;

    const float Dh = Dp[h];
    const size_t rowbase = (size_t)b * SEQ;

    for (int l0 = 0; l0 < SEQ; l0 += 16) {
        // cooperative load of 16 timesteps of xh / B / C
#pragma unroll
        for (int i = tid; i < 16 * 64; i += 256) {
            const int t = i >> 6, j = i & 63;
            const size_t r = (rowbase + l0 + t) * (size_t)CDIM;
            sX[t][j] = g_conv[r + h * 64 + j];
            sB[t][j] = g_conv[r + DI + j];
            sC[t][j] = g_conv[r + DI + NSTATE + j];
        }
        if (tid < 16) {
            const size_t r = rowbase + l0 + tid;
            sdt[tid] = g_dt[r * NH + h];
            sda[tid] = g_dA[r * NH + h];
        }
        __syncthreads();

#pragma unroll
        for (int t = 0; t < 16; t++) {
            const float xv  = sX[t][p];
            const float dtx = sdt[t] * xv;
            const float dav = sda[t];
            float acc = 0.f;
            const float4* Bv = (const float4*)&sB[t][nb];
            const float4* Cv = (const float4*)&sC[t][nb];
#pragma unroll
            for (int q = 0; q < 4; q++) {
                const float4 bq = Bv[q];
                const float4 cq = Cv[q];
                st[4*q+0] = dav * st[4*q+0] + dtx * bq.x; acc = fmaf(st[4*q+0], cq.x, acc);
                st[4*q+1] = dav * st[4*q+1] + dtx * bq.y; acc = fmaf(st[4*q+1], cq.y, acc);
                st[4*q+2] = dav * st[4*q+2] + dtx * bq.z; acc = fmaf(st[4*q+2], cq.z, acc);
                st[4*q+3] = dav * st[4*q+3] + dtx * bq.w; acc = fmaf(st[4*q+3], cq.w, acc);
            }
            acc += __shfl_xor_sync(0xffffffffu, acc, 1);
            acc += __shfl_xor_sync(0xffffffffu, acc, 2);
            if (g == 0) sY[t][p] = acc;
        }
        __syncthreads();

        // coalesced store (add D * xh skip term)
#pragma unroll
        for (int i = tid; i < 16 * 64; i += 256) {
            const int t = i >> 6, j = i & 63;
            g_y[(rowbase + l0 + t) * (size_t)DI + h * 64 + j] = sY[t][j] + Dh * sX[t][j];
        }
        __syncthreads();
    }
}

// ---------------- gate (silu(z)) + RMSNorm, in place on g_y ----------------
__global__ void gaterms_kernel(const float* __restrict__ rw)
{
    __shared__ float sh[8];
    const int row = blockIdx.x;
    const int tid = threadIdx.x;
    float* yr = g_y + (size_t)row * DI;
    const float* zr = g_zx + (size_t)row * DIP;
    float vals[8];
    float s2 = 0.f;
#pragma unroll
    for (int u = 0; u < 2; u++) {
        const int j = tid * 4 + u * 1024;
        const float4 yv = *(const float4*)(yr + j);
        const float4 zv = *(const float4*)(zr + j);
        const float g0 = yv.x * (zv.x / (1.f + expf(-zv.x)));
        const float g1 = yv.y * (zv.y / (1.f + expf(-zv.y)));
        const float g2 = yv.z * (zv.z / (1.f + expf(-zv.z)));
        const float g3 = yv.w * (zv.w / (1.f + expf(-zv.w)));
        vals[u*4+0] = g0; vals[u*4+1] = g1; vals[u*4+2] = g2; vals[u*4+3] = g3;
        s2 += g0*g0 + g1*g1 + g2*g2 + g3*g3;
    }
#pragma unroll
    for (int o = 16; o; o >>= 1) s2 += __shfl_xor_sync(0xffffffffu, s2, o);
    if ((tid & 31) == 0) sh[tid >> 5] = s2;
    __syncthreads();
    if (tid < 32) {
        s2 = (tid < 8) ? sh[tid] : 0.f;
#pragma unroll
        for (int o = 4; o; o >>= 1) s2 += __shfl_xor_sync(0xffffffffu, s2, o);
        if (tid == 0) sh[0] = s2;
    }
    __syncthreads();
    const float scale = rsqrtf(sh[0] * (1.f / DI) + 1e-5f);
#pragma unroll
    for (int u = 0; u < 2; u++) {
        const int j = tid * 4 + u * 1024;
        const float4 wv = *(const float4*)(rw + j);
        float4 o;
        o.x = vals[u*4+0] * scale * wv.x;
        o.y = vals[u*4+1] * scale * wv.y;
        o.z = vals[u*4+2] * scale * wv.z;
        o.w = vals[u*4+3] * scale * wv.w;
        *(float4*)(yr + j) = o;
    }
}

// ---------------- host launch ----------------
extern "C" void kernel_launch(void* const* d_in, const int* in_sizes, int n_in,
                              void* d_out, int out_size)
{
    const float* x       = (const float*)d_in[0];
    const float* ln_w    = (const float*)d_in[1];
    const float* ln_b    = (const float*)d_in[2];
    const float* in_proj = (const float*)d_in[3];
    const float* conv_w  = (const float*)d_in[4];
    const float* conv_b  = (const float*)d_in[5];
    const float* dt_bias = (const float*)d_in[6];
    const float* A_log   = (const float*)d_in[7];
    const float* Dvec    = (const float*)d_in[8];
    const float* rms_w   = (const float*)d_in[9];
    const float* out_w   = (const float*)d_in[10];
    float* out = (float*)d_out;

    float *p_ln, *p_zx, *p_y, *p_h;
    cudaGetSymbolAddress((void**)&p_ln, g_ln);
    cudaGetSymbolAddress((void**)&p_zx, g_zx);
    cudaGetSymbolAddress((void**)&p_y,  g_y);
    cudaGetSymbolAddress((void**)&p_h,  g_h);

    for (int i = 0; i < 2; i++) {
        const float* hin  = (i == 0) ? x   : p_h;
        float*       hout = (i == 0) ? p_h : out;

        ln_kernel<<<M_ROWS, 256>>>(hin, ln_w + i * DM, ln_b + i * DM, p_ln);

        gemm_nt<<<dim3((DIP + 127) / 128, M_ROWS / 128), 256>>>(
            p_ln, in_proj + (size_t)i * DIP * DM, nullptr, p_zx, M_ROWS, DIP, DM);

        dt_kernel<<<(M_ROWS * NH) / 256, 256>>>(dt_bias + i * NH, A_log + i * NH);

        conv_kernel<<<(M_ROWS * CDIM + 255) / 256, 256>>>(
            conv_w + (size_t)i * CDIM * 4, conv_b + (size_t)i * CDIM);

        scan_kernel<<<BATCH * NH, 256>>>(Dvec + i * NH);

        gaterms_kernel<<<M_ROWS, 256>>>(rms_w + (size_t)i * DI);

        gemm_nt<<<dim3(DM / 128, M_ROWS / 128), 256>>>(
            p_y, out_w + (size_t)i * DM * DI, hin, hout, M_ROWS, DM, DI);
    }
}

// round 4
// speedup vs baseline: 1.0223x; 1.0223x over previous
#include <cuda_runtime.h>
#include <math.h>

#define BATCH 2
#define SEQ   4096
#define DM    1024
#define DIP   4256
#define DI    2048
#define CDIM  2176
#define NH    32
#define HD    64
#define NSTATE 64
#define M_ROWS (BATCH*SEQ)   /* 8192 */

typedef unsigned long long ull;

// ---------------- scratch (device globals; no allocations allowed) ----------------
__device__ float g_ln[(size_t)M_ROWS * DM];
__device__ float g_zx[(size_t)M_ROWS * DIP];
__device__ float g_conv[(size_t)M_ROWS * CDIM];
__device__ float g_dt[(size_t)M_ROWS * NH];
__device__ float g_dA[(size_t)M_ROWS * NH];
__device__ float g_y[(size_t)M_ROWS * DI];
__device__ float g_h[(size_t)M_ROWS * DM];

// packed f32x2 FMA (sm_103a; ptxas never emits this on its own)
__device__ __forceinline__ ull ffma2(ull a, ull b, ull c) {
    ull d;
    asm("fma.rn.f32x2 %0, %1, %2, %3;" : "=l"(d) : "l"(a), "l"(b), "l"(c));
    return d;
}
__device__ __forceinline__ ull dup2(float x) {
    ull d;
    asm("mov.b64 %0, {%1, %1};" : "=l"(d) : "r"(__float_as_int(x)));
    return d;
}

// ---------------- LayerNorm: one block per row of 1024 ----------------
__global__ void ln_kernel(const float* __restrict__ x, const float* __restrict__ w,
                          const float* __restrict__ b, float* __restrict__ out)
{
    __shared__ float sh1[8], sh2[8];
    const int row = blockIdx.x;
    const int tid = threadIdx.x;
    const float4 v = ((const float4*)(x + (size_t)row * DM))[tid];
    float s1 = v.x + v.y + v.z + v.w;
    float s2 = v.x*v.x + v.y*v.y + v.z*v.z + v.w*v.w;
#pragma unroll
    for (int o = 16; o; o >>= 1) {
        s1 += __shfl_xor_sync(0xffffffffu, s1, o);
        s2 += __shfl_xor_sync(0xffffffffu, s2, o);
    }
    if ((tid & 31) == 0) { sh1[tid >> 5] = s1; sh2[tid >> 5] = s2; }
    __syncthreads();
    if (tid < 32) {
        s1 = (tid < 8) ? sh1[tid] : 0.f;
        s2 = (tid < 8) ? sh2[tid] : 0.f;
#pragma unroll
        for (int o = 4; o; o >>= 1) {
            s1 += __shfl_xor_sync(0xffffffffu, s1, o);
            s2 += __shfl_xor_sync(0xffffffffu, s2, o);
        }
        if (tid == 0) { sh1[0] = s1; sh2[0] = s2; }
    }
    __syncthreads();
    const float mean = sh1[0] * (1.f / DM);
    const float var  = sh2[0] * (1.f / DM) - mean * mean;
    const float rstd = rsqrtf(var + 1e-5f);
    const float4 wv = ((const float4*)w)[tid];
    const float4 bv = ((const float4*)b)[tid];
    float4 o;
    o.x = (v.x - mean) * rstd * wv.x + bv.x;
    o.y = (v.y - mean) * rstd * wv.y + bv.y;
    o.z = (v.z - mean) * rstd * wv.z + bv.z;
    o.w = (v.w - mean) * rstd * wv.w + bv.w;
    ((float4*)(out + (size_t)row * DM))[tid] = o;
}

// ---------------- NT GEMM: C[M,N] = A[M,K] * B[N,K]^T (+Res) ----------------
// 128x128 tile, BK=8, 256 threads, 8x8 per thread via packed f32x2 FMA.
// Double-buffered SMEM, register prefetch, one sync per K-tile.
__global__ __launch_bounds__(256, 2)
void gemm_nt(const float* __restrict__ A, const float* __restrict__ Bw,
             const float* __restrict__ Res, float* __restrict__ C,
             int M, int N, int K)
{
    __shared__ float As[2][8][128];
    __shared__ float Bs[2][8][128];
    const int tid = threadIdx.x;
    const int bm = blockIdx.y * 128;
    const int bn = blockIdx.x * 128;
    const int tx = tid & 15;
    const int ty = tid >> 4;
    const int lr = tid >> 1;          // 0..127 row within tile
    const int lk = (tid & 1) * 4;     // 0 or 4

    ull acc[8][4];
#pragma unroll
    for (int i = 0; i < 8; i++)
#pragma unroll
        for (int j = 0; j < 4; j++) acc[i][j] = 0ull;

    const float* Ap = A + (size_t)(bm + lr) * K + lk;
    const bool  bok = (bn + lr) < N;
    const float* Bp = Bw + (size_t)(bok ? (bn + lr) : 0) * K + lk;

    // preload first K-tile
    {
        const float4 av = *(const float4*)(Ap);
        float4 bv = make_float4(0.f, 0.f, 0.f, 0.f);
        if (bok) bv = *(const float4*)(Bp);
        As[0][lk+0][lr] = av.x; As[0][lk+1][lr] = av.y; As[0][lk+2][lr] = av.z; As[0][lk+3][lr] = av.w;
        Bs[0][lk+0][lr] = bv.x; Bs[0][lk+1][lr] = bv.y; Bs[0][lk+2][lr] = bv.z; Bs[0][lk+3][lr] = bv.w;
    }
    __syncthreads();

    int buf = 0;
    for (int k0 = 0; k0 < K; k0 += 8) {
        const bool has_next = (k0 + 8) < K;
        float4 anx, bnx;
        if (has_next) {
            anx = *(const float4*)(Ap + k0 + 8);
            bnx = make_float4(0.f, 0.f, 0.f, 0.f);
            if (bok) bnx = *(const float4*)(Bp + k0 + 8);
        }

#pragma unroll
        for (int kk = 0; kk < 8; kk++) {
            float a[8];
            *(float4*)(a + 0) = *(const float4*)&As[buf][kk][ty * 4];
            *(float4*)(a + 4) = *(const float4*)&As[buf][kk][64 + ty * 4];
            ull b2[4];
            {
                const ull* b0 = (const ull*)&Bs[buf][kk][tx * 4];
                const ull* b1 = (const ull*)&Bs[buf][kk][64 + tx * 4];
                b2[0] = b0[0]; b2[1] = b0[1];
                b2[2] = b1[0]; b2[3] = b1[1];
            }
#pragma unroll
            for (int i = 0; i < 8; i++) {
                const ull aa = dup2(a[i]);
#pragma unroll
                for (int j = 0; j < 4; j++)
                    acc[i][j] = ffma2(aa, b2[j], acc[i][j]);
            }
        }

        if (has_next) {
            const int nb = buf ^ 1;
            As[nb][lk+0][lr] = anx.x; As[nb][lk+1][lr] = anx.y; As[nb][lk+2][lr] = anx.z; As[nb][lk+3][lr] = anx.w;
            Bs[nb][lk+0][lr] = bnx.x; Bs[nb][lk+1][lr] = bnx.y; Bs[nb][lk+2][lr] = bnx.z; Bs[nb][lk+3][lr] = bnx.w;
        }
        __syncthreads();
        buf ^= 1;
    }

    // epilogue: acc[r][0..1] -> cols bn+tx*4..+3 ; acc[r][2..3] -> cols bn+64+tx*4..+3
#pragma unroll
    for (int ih = 0; ih < 2; ih++)
#pragma unroll
    for (int i = 0; i < 4; i++) {
        const int r = ih * 4 + i;
        const int m = bm + ih * 64 + ty * 4 + i;
#pragma unroll
        for (int jh = 0; jh < 2; jh++) {
            const int n = bn + jh * 64 + tx * 4;
            if (n < N) {
                const float2 p0 = *(const float2*)&acc[r][jh * 2 + 0];
                const float2 p1 = *(const float2*)&acc[r][jh * 2 + 1];
                float4 v = make_float4(p0.x, p0.y, p1.x, p1.y);
                if (Res) {
                    const float4 rr = *(const float4*)&Res[(size_t)m * N + n];
                    v.x += rr.x; v.y += rr.y; v.z += rr.z; v.w += rr.w;
                }
                *(float4*)&C[(size_t)m * N + n] = v;
            }
        }
    }
}

// ---------------- dt/softplus/dA ----------------
__global__ void dt_kernel(const float* __restrict__ dt_bias, const float* __restrict__ A_log)
{
    const int idx = blockIdx.x * blockDim.x + threadIdx.x;  // < M_ROWS*NH
    const int h = idx & (NH - 1);
    const int row = idx >> 5;
    const float raw = g_zx[(size_t)row * DIP + (DI + CDIM) + h] + dt_bias[h];
    const float dt = (raw > 20.f) ? raw : log1pf(expf(raw));
    const float A = -expf(A_log[h]);
    g_dt[idx] = dt;
    g_dA[idx] = expf(dt * A);
}

// ---------------- causal depthwise conv (d=4) + bias + SiLU ----------------
__global__ void conv_kernel(const float* __restrict__ cw, const float* __restrict__ cb)
{
    const int idx = blockIdx.x * blockDim.x + threadIdx.x;
    if (idx >= M_ROWS * CDIM) return;
    const int c = idx % CDIM;
    const int row = idx / CDIM;
    const int l = row & (SEQ - 1);
    const float w0 = cw[c*4+0], w1 = cw[c*4+1], w2 = cw[c*4+2], w3 = cw[c*4+3];
    float acc = cb[c];
    const size_t base = (size_t)row * DIP + DI + c;
    acc += g_zx[base] * w3;
    if (l >= 1) acc += g_zx[base - (size_t)DIP]     * w2;
    if (l >= 2) acc += g_zx[base - 2*(size_t)DIP]   * w1;
    if (l >= 3) acc += g_zx[base - 3*(size_t)DIP]   * w0;
    g_conv[idx] = acc * (1.f / (1.f + expf(-acc)));
}

// ---------------- sequential selective scan: one CTA per (b,h) ----------------
// 256 threads: thread (p = tid>>2, g = tid&3) owns state[p][g*16 : g*16+16]
__global__ __launch_bounds__(256, 1)
void scan_kernel(const float* __restrict__ Dp)
{
    const int bh = blockIdx.x;
    const int b = bh >> 5, h = bh & 31;
    const int tid = threadIdx.x;
    const int p = tid >> 2, g = tid & 3, nb = g * 16;

    __shared__ float sX[16][64], sB[16][64], sC[16][64], sY[16][64];
    __shared__ float sdt[16], sda[16];

    float st[16];
#pragma unroll
    for (int i = 0; i < 16; i++) st[i] = 0.f;

    const float Dh = Dp[h];
    const size_t rowbase = (size_t)b * SEQ;

    for (int l0 = 0; l0 < SEQ; l0 += 16) {
        // cooperative load of 16 timesteps of xh / B / C
#pragma unroll
        for (int i = tid; i < 16 * 64; i += 256) {
            const int t = i >> 6, j = i & 63;
            const size_t r = (rowbase + l0 + t) * (size_t)CDIM;
            sX[t][j] = g_conv[r + h * 64 + j];
            sB[t][j] = g_conv[r + DI + j];
            sC[t][j] = g_conv[r + DI + NSTATE + j];
        }
        if (tid < 16) {
            const size_t r = rowbase + l0 + tid;
            sdt[tid] = g_dt[r * NH + h];
            sda[tid] = g_dA[r * NH + h];
        }
        __syncthreads();

#pragma unroll
        for (int t = 0; t < 16; t++) {
            const float xv  = sX[t][p];
            const float dtx = sdt[t] * xv;
            const float dav = sda[t];
            float acc = 0.f;
            const float4* Bv = (const float4*)&sB[t][nb];
            const float4* Cv = (const float4*)&sC[t][nb];
#pragma unroll
            for (int q = 0; q < 4; q++) {
                const float4 bq = Bv[q];
                const float4 cq = Cv[q];
                st[4*q+0] = dav * st[4*q+0] + dtx * bq.x; acc = fmaf(st[4*q+0], cq.x, acc);
                st[4*q+1] = dav * st[4*q+1] + dtx * bq.y; acc = fmaf(st[4*q+1], cq.y, acc);
                st[4*q+2] = dav * st[4*q+2] + dtx * bq.z; acc = fmaf(st[4*q+2], cq.z, acc);
                st[4*q+3] = dav * st[4*q+3] + dtx * bq.w; acc = fmaf(st[4*q+3], cq.w, acc);
            }
            acc += __shfl_xor_sync(0xffffffffu, acc, 1);
            acc += __shfl_xor_sync(0xffffffffu, acc, 2);
            if (g == 0) sY[t][p] = acc;
        }
        __syncthreads();

        // coalesced store (add D * xh skip term)
#pragma unroll
        for (int i = tid; i < 16 * 64; i += 256) {
            const int t = i >> 6, j = i & 63;
            g_y[(rowbase + l0 + t) * (size_t)DI + h * 64 + j] = sY[t][j] + Dh * sX[t][j];
        }
        __syncthreads();
    }
}

// ---------------- gate (silu(z)) + RMSNorm, in place on g_y ----------------
__global__ void gaterms_kernel(const float* __restrict__ rw)
{
    __shared__ float sh[8];
    const int row = blockIdx.x;
    const int tid = threadIdx.x;
    float* yr = g_y + (size_t)row * DI;
    const float* zr = g_zx + (size_t)row * DIP;
    float vals[8];
    float s2 = 0.f;
#pragma unroll
    for (int u = 0; u < 2; u++) {
        const int j = tid * 4 + u * 1024;
        const float4 yv = *(const float4*)(yr + j);
        const float4 zv = *(const float4*)(zr + j);
        const float g0 = yv.x * (zv.x / (1.f + expf(-zv.x)));
        const float g1 = yv.y * (zv.y / (1.f + expf(-zv.y)));
        const float g2 = yv.z * (zv.z / (1.f + expf(-zv.z)));
        const float g3 = yv.w * (zv.w / (1.f + expf(-zv.w)));
        vals[u*4+0] = g0; vals[u*4+1] = g1; vals[u*4+2] = g2; vals[u*4+3] = g3;
        s2 += g0*g0 + g1*g1 + g2*g2 + g3*g3;
    }
#pragma unroll
    for (int o = 16; o; o >>= 1) s2 += __shfl_xor_sync(0xffffffffu, s2, o);
    if ((tid & 31) == 0) sh[tid >> 5] = s2;
    __syncthreads();
    if (tid < 32) {
        s2 = (tid < 8) ? sh[tid] : 0.f;
#pragma unroll
        for (int o = 4; o; o >>= 1) s2 += __shfl_xor_sync(0xffffffffu, s2, o);
        if (tid == 0) sh[0] = s2;
    }
    __syncthreads();
    const float scale = rsqrtf(sh[0] * (1.f / DI) + 1e-5f);
#pragma unroll
    for (int u = 0; u < 2; u++) {
        const int j = tid * 4 + u * 1024;
        const float4 wv = *(const float4*)(rw + j);
        float4 o;
        o.x = vals[u*4+0] * scale * wv.x;
        o.y = vals[u*4+1] * scale * wv.y;
        o.z = vals[u*4+2] * scale * wv.z;
        o.w = vals[u*4+3] * scale * wv.w;
        *(float4*)(yr + j) = o;
    }
}

// ---------------- host launch ----------------
extern "C" void kernel_launch(void* const* d_in, const int* in_sizes, int n_in,
                              void* d_out, int out_size)
{
    const float* x       = (const float*)d_in[0];
    const float* ln_w    = (const float*)d_in[1];
    const float* ln_b    = (const float*)d_in[2];
    const float* in_proj = (const float*)d_in[3];
    const float* conv_w  = (const float*)d_in[4];
    const float* conv_b  = (const float*)d_in[5];
    const float* dt_bias = (const float*)d_in[6];
    const float* A_log   = (const float*)d_in[7];
    const float* Dvec    = (const float*)d_in[8];
    const float* rms_w   = (const float*)d_in[9];
    const float* out_w   = (const float*)d_in[10];
    float* out = (float*)d_out;

    float *p_ln, *p_zx, *p_y, *p_h;
    cudaGetSymbolAddress((void**)&p_ln, g_ln);
    cudaGetSymbolAddress((void**)&p_zx, g_zx);
    cudaGetSymbolAddress((void**)&p_y,  g_y);
    cudaGetSymbolAddress((void**)&p_h,  g_h);

    for (int i = 0; i < 2; i++) {
        const float* hin  = (i == 0) ? x   : p_h;
        float*       hout = (i == 0) ? p_h : out;

        ln_kernel<<<M_ROWS, 256>>>(hin, ln_w + i * DM, ln_b + i * DM, p_ln);

        gemm_nt<<<dim3((DIP + 127) / 128, M_ROWS / 128), 256>>>(
            p_ln, in_proj + (size_t)i * DIP * DM, nullptr, p_zx, M_ROWS, DIP, DM);

        dt_kernel<<<(M_ROWS * NH) / 256, 256>>>(dt_bias + i * NH, A_log + i * NH);

        conv_kernel<<<(M_ROWS * CDIM + 255) / 256, 256>>>(
            conv_w + (size_t)i * CDIM * 4, conv_b + (size_t)i * CDIM);

        scan_kernel<<<BATCH * NH, 256>>>(Dvec + i * NH);

        gaterms_kernel<<<M_ROWS, 256>>>(rms_w + (size_t)i * DI);

        gemm_nt<<<dim3(DM / 128, M_ROWS / 128), 256>>>(
            p_y, out_w + (size_t)i * DM * DI, hin, hout, M_ROWS, DM, DI);
    }
}

// round 6
// speedup vs baseline: 1.4355x; 1.4041x over previous
#include <cuda_runtime.h>
#include <cuda_bf16.h>
#include <math.h>
#include <stdint.h>

#define BATCH 2
#define SEQ   4096
#define DM    1024
#define DIP   4256
#define DI    2048
#define CDIM  2176
#define NH    32
#define HD    64
#define NSTATE 64
#define M_ROWS (BATCH*SEQ)   /* 8192 */

// ---------------- scratch (device globals; no allocations allowed) ----------------
__device__ float g_zx[(size_t)M_ROWS * DIP];
__device__ float g_conv[(size_t)M_ROWS * CDIM];
__device__ float g_dt[(size_t)M_ROWS * NH];
__device__ float g_dA[(size_t)M_ROWS * NH];
__device__ float g_y[(size_t)M_ROWS * DI];
__device__ float g_h[(size_t)M_ROWS * DM];
__device__ __nv_bfloat16 g_xhi[(size_t)M_ROWS * DM];
__device__ __nv_bfloat16 g_xlo[(size_t)M_ROWS * DM];
__device__ __nv_bfloat16 g_yhi[(size_t)M_ROWS * DI];
__device__ __nv_bfloat16 g_ylo[(size_t)M_ROWS * DI];
__device__ __nv_bfloat16 g_whi[(size_t)DIP * DM];
__device__ __nv_bfloat16 g_wlo[(size_t)DIP * DM];

// ---------------- baseline-ISA PTX helpers (no sm_103a-only features) ----------------
__device__ __forceinline__ uint32_t smem_u32_of(const void* p) {
    uint32_t a;
    asm("{ .reg .u64 t; cvta.to.shared.u64 t, %1; cvt.u32.u64 %0, t; }" : "=r"(a) : "l"(p));
    return a;
}
__device__ __forceinline__ void cp16(uint32_t dst, const void* src) {
    asm volatile("cp.async.cg.shared.global [%0], [%1], 16;" :: "r"(dst), "l"(src));
}
__device__ __forceinline__ void cp_commit() {
    asm volatile("cp.async.commit_group;" ::: "memory");
}
template<int N> __device__ __forceinline__ void cp_wait() {
    asm volatile("cp.async.wait_group %0;" :: "n"(N) : "memory");
}
__device__ __forceinline__ void ldsm_x4(uint32_t* r, uint32_t addr) {
    asm volatile("ldmatrix.sync.aligned.m8n8.x4.shared.b16 {%0,%1,%2,%3}, [%4];"
                 : "=r"(r[0]), "=r"(r[1]), "=r"(r[2]), "=r"(r[3]) : "r"(addr));
}
__device__ __forceinline__ void mma16816(float* d, const uint32_t* a, uint32_t b0, uint32_t b1) {
    asm volatile("mma.sync.aligned.m16n8k16.row.col.f32.bf16.bf16.f32 "
                 "{%0,%1,%2,%3}, {%4,%5,%6,%7}, {%8,%9}, {%0,%1,%2,%3};"
                 : "+f"(d[0]), "+f"(d[1]), "+f"(d[2]), "+f"(d[3])
                 : "r"(a[0]), "r"(a[1]), "r"(a[2]), "r"(a[3]), "r"(b0), "r"(b1));
}

__device__ __forceinline__ void split_bf(float v, __nv_bfloat16& h, __nv_bfloat16& l) {
    h = __float2bfloat16(v);
    l = __float2bfloat16(v - __bfloat162float(h));
}

// ---------------- weight fp32 -> (hi, lo) bf16 ----------------
__global__ void cvt_hilo(const float* __restrict__ s, __nv_bfloat16* __restrict__ hi,
                         __nv_bfloat16* __restrict__ lo)
{
    const size_t idx = (size_t)blockIdx.x * blockDim.x + threadIdx.x;
    const float4 v = ((const float4*)s)[idx];
    __nv_bfloat16 h0,h1,h2,h3,l0,l1,l2,l3;
    split_bf(v.x,h0,l0); split_bf(v.y,h1,l1); split_bf(v.z,h2,l2); split_bf(v.w,h3,l3);
    __nv_bfloat162 a,b;
    a.x=h0; a.y=h1; b.x=h2; b.y=h3;
    ((__nv_bfloat162*)hi)[idx*2]=a; ((__nv_bfloat162*)hi)[idx*2+1]=b;
    a.x=l0; a.y=l1; b.x=l2; b.y=l3;
    ((__nv_bfloat162*)lo)[idx*2]=a; ((__nv_bfloat162*)lo)[idx*2+1]=b;
}

// ---------------- HMMA bf16-split GEMM ----------------
// C[M,Nn] = A[M,K]*W[Nn,K]^T (+Res), A/W as bf16 hi/lo. 3-term compensated product.
// 128x128 CTA tile, BK=32, 8 warps (4x2), warp tile 32x64, mma.sync m16n8k16.
// SMEM rows padded to 144B (conflict-free ldmatrix). Double-buffered cp.async.
#define ROWB   144
#define MAT_SZ (128 * ROWB)              /* 18432 */
#define OFF_AH 0
#define OFF_AL (1 * MAT_SZ)
#define OFF_BH (2 * MAT_SZ)
#define OFF_BL (3 * MAT_SZ)
#define BUFSZ  (4 * MAT_SZ)              /* 73728 */
#define GEMM_SMEM (2 * BUFSZ)            /* 147456 */

__global__ __launch_bounds__(256, 1)
void gemm_mma(const __nv_bfloat16* __restrict__ Ahi, const __nv_bfloat16* __restrict__ Alo,
              const __nv_bfloat16* __restrict__ Whi, const __nv_bfloat16* __restrict__ Wlo,
              const float* __restrict__ Res, float* __restrict__ C,
              int Nn, int K)
{
    extern __shared__ char smem[];
    const uint32_t sb = smem_u32_of(smem);
    const int tid  = threadIdx.x;
    const int wid  = tid >> 5;
    const int lane = tid & 31;
    const int bm = blockIdx.y * 128;
    const int bn = blockIdx.x * 128;
    const int wm = wid >> 1;           // 0..3 -> 32-row band
    const int wn = wid & 1;            // 0..1 -> 64-col band
    const int NC = K >> 5;

    float acc[2][8][4];
#pragma unroll
    for (int i = 0; i < 2; i++)
#pragma unroll
        for (int j = 0; j < 8; j++)
#pragma unroll
            for (int q = 0; q < 4; q++) acc[i][j][q] = 0.f;

    // global->smem load mapping: thread -> row lr (0..127), chunk pair lc
    const int lr = tid >> 1;
    const int lc = (tid & 1) * 2;      // 16B-chunk index base (0 or 2), 4 chunks/row
    int brow = bn + lr; if (brow >= Nn) brow = Nn - 1;
    const __nv_bfloat16* pah = Ahi + (size_t)(bm + lr) * K;
    const __nv_bfloat16* pal = Alo + (size_t)(bm + lr) * K;
    const __nv_bfloat16* pbh = Whi + (size_t)brow * K;
    const __nv_bfloat16* pbl = Wlo + (size_t)brow * K;

#define LOAD_CHUNK(c) do {                                            \
    const uint32_t s0 = sb + ((c) & 1) * BUFSZ + lr * ROWB;           \
    const int kof = (c) * 32;                                         \
    _Pragma("unroll")                                                 \
    for (int q = 0; q < 2; q++) {                                     \
        const int ch = lc + q;                                        \
        cp16(s0 + OFF_AH + ch * 16, pah + kof + ch * 8);              \
        cp16(s0 + OFF_AL + ch * 16, pal + kof + ch * 8);              \
        cp16(s0 + OFF_BH + ch * 16, pbh + kof + ch * 8);              \
        cp16(s0 + OFF_BL + ch * 16, pbl + kof + ch * 8);              \
    }                                                                 \
    cp_commit();                                                      \
} while (0)

    LOAD_CHUNK(0);
    if (NC > 1) LOAD_CHUNK(1);

    // ldmatrix per-lane selectors
    const int a_row = wm * 32 + (lane & 15);
    const int a_chk = lane >> 4;                     // 0/1 -> k half
    const int b_row = wn * 64 + ((lane >> 4) << 3) + (lane & 7);
    const int b_chk = (lane >> 3) & 1;

    for (int c = 0; c < NC; c++) {
        if (c + 1 < NC) cp_wait<1>(); else cp_wait<0>();
        __syncthreads();
        const uint32_t sbuf = sb + (c & 1) * BUFSZ;

#pragma unroll
        for (int ks = 0; ks < 2; ks++) {
            uint32_t ah[2][4], al[2][4];
#pragma unroll
            for (int im = 0; im < 2; im++) {
                const uint32_t addr = sbuf + (a_row + im * 16) * ROWB + (ks * 2 + a_chk) * 16;
                ldsm_x4(ah[im], addr + OFF_AH);
                ldsm_x4(al[im], addr + OFF_AL);
            }
            uint32_t bh[4][4], bl[4][4];
#pragma unroll
            for (int g = 0; g < 4; g++) {
                const uint32_t addr = sbuf + (b_row + g * 16) * ROWB + (ks * 2 + b_chk) * 16;
                ldsm_x4(bh[g], addr + OFF_BH);
                ldsm_x4(bl[g], addr + OFF_BL);
            }
#pragma unroll
            for (int im = 0; im < 2; im++)
#pragma unroll
                for (int g = 0; g < 4; g++)
#pragma unroll
                    for (int hf = 0; hf < 2; hf++) {
                        float* d = acc[im][g * 2 + hf];
                        mma16816(d, ah[im], bh[g][hf*2], bh[g][hf*2+1]);
                        mma16816(d, ah[im], bl[g][hf*2], bl[g][hf*2+1]);
                        mma16816(d, al[im], bh[g][hf*2], bh[g][hf*2+1]);
                    }
        }
        __syncthreads();
        if (c + 2 < NC) LOAD_CHUNK(c + 2);
    }
#undef LOAD_CHUNK

    // epilogue: frag (d0,d1)->row r0, (d2,d3)->row r0+8; cols n0 + (lane&3)*2
#pragma unroll
    for (int im = 0; im < 2; im++) {
        const int r0 = bm + wm * 32 + im * 16 + (lane >> 2);
#pragma unroll
        for (int j = 0; j < 8; j++) {
            const int n0 = bn + wn * 64 + j * 8;
            if (n0 < Nn) {
                const int cc = n0 + (lane & 3) * 2;
                float2 v0 = make_float2(acc[im][j][0], acc[im][j][1]);
                float2 v1 = make_float2(acc[im][j][2], acc[im][j][3]);
                if (Res) {
                    const float2 r0v = *(const float2*)&Res[(size_t)r0 * Nn + cc];
                    const float2 r1v = *(const float2*)&Res[(size_t)(r0 + 8) * Nn + cc];
                    v0.x += r0v.x; v0.y += r0v.y;
                    v1.x += r1v.x; v1.y += r1v.y;
                }
                *(float2*)&C[(size_t)r0 * Nn + cc] = v0;
                *(float2*)&C[(size_t)(r0 + 8) * Nn + cc] = v1;
            }
        }
    }
}

// ---------------- LayerNorm -> bf16 hi/lo ----------------
__global__ void ln_kernel(const float* __restrict__ x, const float* __restrict__ w,
                          const float* __restrict__ b,
                          __nv_bfloat16* __restrict__ ohi, __nv_bfloat16* __restrict__ olo)
{
    __shared__ float sh1[8], sh2[8];
    const int row = blockIdx.x;
    const int tid = threadIdx.x;
    const float4 v = ((const float4*)(x + (size_t)row * DM))[tid];
    float s1 = v.x + v.y + v.z + v.w;
    float s2 = v.x*v.x + v.y*v.y + v.z*v.z + v.w*v.w;
#pragma unroll
    for (int o = 16; o; o >>= 1) {
        s1 += __shfl_xor_sync(0xffffffffu, s1, o);
        s2 += __shfl_xor_sync(0xffffffffu, s2, o);
    }
    if ((tid & 31) == 0) { sh1[tid >> 5] = s1; sh2[tid >> 5] = s2; }
    __syncthreads();
    if (tid < 32) {
        s1 = (tid < 8) ? sh1[tid] : 0.f;
        s2 = (tid < 8) ? sh2[tid] : 0.f;
#pragma unroll
        for (int o = 4; o; o >>= 1) {
            s1 += __shfl_xor_sync(0xffffffffu, s1, o);
            s2 += __shfl_xor_sync(0xffffffffu, s2, o);
        }
        if (tid == 0) { sh1[0] = s1; sh2[0] = s2; }
    }
    __syncthreads();
    const float mean = sh1[0] * (1.f / DM);
    const float var  = sh2[0] * (1.f / DM) - mean * mean;
    const float rstd = rsqrtf(var + 1e-5f);
    const float4 wv = ((const float4*)w)[tid];
    const float4 bv = ((const float4*)b)[tid];
    float o0 = (v.x - mean) * rstd * wv.x + bv.x;
    float o1 = (v.y - mean) * rstd * wv.y + bv.y;
    float o2 = (v.z - mean) * rstd * wv.z + bv.z;
    float o3 = (v.w - mean) * rstd * wv.w + bv.w;
    __nv_bfloat16 h0,h1,h2,h3,l0,l1,l2,l3;
    split_bf(o0,h0,l0); split_bf(o1,h1,l1); split_bf(o2,h2,l2); split_bf(o3,h3,l3);
    __nv_bfloat162 p;
    __nv_bfloat162* hp = (__nv_bfloat162*)(ohi + (size_t)row * DM) + tid * 2;
    __nv_bfloat162* lp = (__nv_bfloat162*)(olo + (size_t)row * DM) + tid * 2;
    p.x=h0; p.y=h1; hp[0]=p;  p.x=h2; p.y=h3; hp[1]=p;
    p.x=l0; p.y=l1; lp[0]=p;  p.x=l2; p.y=l3; lp[1]=p;
}

// ---------------- dt/softplus/dA ----------------
__global__ void dt_kernel(const float* __restrict__ dt_bias, const float* __restrict__ A_log)
{
    const int idx = blockIdx.x * blockDim.x + threadIdx.x;
    const int h = idx & (NH - 1);
    const int row = idx >> 5;
    const float raw = g_zx[(size_t)row * DIP + (DI + CDIM) + h] + dt_bias[h];
    const float dt = (raw > 20.f) ? raw : log1pf(expf(raw));
    const float A = -expf(A_log[h]);
    g_dt[idx] = dt;
    g_dA[idx] = expf(dt * A);
}

// ---------------- causal depthwise conv (d=4) + bias + SiLU ----------------
__global__ void conv_kernel(const float* __restrict__ cw, const float* __restrict__ cb)
{
    const int idx = blockIdx.x * blockDim.x + threadIdx.x;
    if (idx >= M_ROWS * CDIM) return;
    const int c = idx % CDIM;
    const int row = idx / CDIM;
    const int l = row & (SEQ - 1);
    const float w0 = cw[c*4+0], w1 = cw[c*4+1], w2 = cw[c*4+2], w3 = cw[c*4+3];
    float acc = cb[c];
    const size_t base = (size_t)row * DIP + DI + c;
    acc += g_zx[base] * w3;
    if (l >= 1) acc += g_zx[base - (size_t)DIP]     * w2;
    if (l >= 2) acc += g_zx[base - 2*(size_t)DIP]   * w1;
    if (l >= 3) acc += g_zx[base - 3*(size_t)DIP]   * w0;
    g_conv[idx] = acc * (1.f / (1.f + expf(-acc)));
}

// ---------------- sequential selective scan: one CTA per (b,h) ----------------
__global__ __launch_bounds__(256, 1)
void scan_kernel(const float* __restrict__ Dp)
{
    const int bh = blockIdx.x;
    const int b = bh >> 5, h = bh & 31;
    const int tid = threadIdx.x;
    const int p = tid >> 2, g = tid & 3, nb = g * 16;

    __shared__ float sX[16][64], sB[16][64], sC[16][64], sY[16][64];
    __shared__ float sdt[16], sda[16];

    float st[16];
#pragma unroll
    for (int i = 0; i < 16; i++) st[i] = 0.f;

    const float Dh = Dp[h];
    const size_t rowbase = (size_t)b * SEQ;

    for (int l0 = 0; l0 < SEQ; l0 += 16) {
#pragma unroll
        for (int i = tid; i < 16 * 64; i += 256) {
            const int t = i >> 6, j = i & 63;
            const size_t r = (rowbase + l0 + t) * (size_t)CDIM;
            sX[t][j] = g_conv[r + h * 64 + j];
            sB[t][j] = g_conv[r + DI + j];
            sC[t][j] = g_conv[r + DI + NSTATE + j];
        }
        if (tid < 16) {
            const size_t r = rowbase + l0 + tid;
            sdt[tid] = g_dt[r * NH + h];
            sda[tid] = g_dA[r * NH + h];
        }
        __syncthreads();

#pragma unroll
        for (int t = 0; t < 16; t++) {
            const float xv  = sX[t][p];
            const float dtx = sdt[t] * xv;
            const float dav = sda[t];
            float acc = 0.f;
            const float4* Bv = (const float4*)&sB[t][nb];
            const float4* Cv = (const float4*)&sC[t][nb];
#pragma unroll
            for (int q = 0; q < 4; q++) {
                const float4 bq = Bv[q];
                const float4 cq = Cv[q];
                st[4*q+0] = dav * st[4*q+0] + dtx * bq.x; acc = fmaf(st[4*q+0], cq.x, acc);
                st[4*q+1] = dav * st[4*q+1] + dtx * bq.y; acc = fmaf(st[4*q+1], cq.y, acc);
                st[4*q+2] = dav * st[4*q+2] + dtx * bq.z; acc = fmaf(st[4*q+2], cq.z, acc);
                st[4*q+3] = dav * st[4*q+3] + dtx * bq.w; acc = fmaf(st[4*q+3], cq.w, acc);
            }
            acc += __shfl_xor_sync(0xffffffffu, acc, 1);
            acc += __shfl_xor_sync(0xffffffffu, acc, 2);
            if (g == 0) sY[t][p] = acc;
        }
        __syncthreads();

#pragma unroll
        for (int i = tid; i < 16 * 64; i += 256) {
            const int t = i >> 6, j = i & 63;
            g_y[(rowbase + l0 + t) * (size_t)DI + h * 64 + j] = sY[t][j] + Dh * sX[t][j];
        }
        __syncthreads();
    }
}

// ---------------- gate (silu(z)) + RMSNorm -> bf16 hi/lo ----------------
__global__ void gaterms_kernel(const float* __restrict__ rw)
{
    __shared__ float sh[8];
    const int row = blockIdx.x;
    const int tid = threadIdx.x;
    const float* yr = g_y + (size_t)row * DI;
    const float* zr = g_zx + (size_t)row * DIP;
    float vals[8];
    float s2 = 0.f;
#pragma unroll
    for (int u = 0; u < 2; u++) {
        const int j = tid * 4 + u * 1024;
        const float4 yv = *(const float4*)(yr + j);
        const float4 zv = *(const float4*)(zr + j);
        const float g0 = yv.x * (zv.x / (1.f + expf(-zv.x)));
        const float g1 = yv.y * (zv.y / (1.f + expf(-zv.y)));
        const float g2 = yv.z * (zv.z / (1.f + expf(-zv.z)));
        const float g3 = yv.w * (zv.w / (1.f + expf(-zv.w)));
        vals[u*4+0] = g0; vals[u*4+1] = g1; vals[u*4+2] = g2; vals[u*4+3] = g3;
        s2 += g0*g0 + g1*g1 + g2*g2 + g3*g3;
    }
#pragma unroll
    for (int o = 16; o; o >>= 1) s2 += __shfl_xor_sync(0xffffffffu, s2, o);
    if ((tid & 31) == 0) sh[tid >> 5] = s2;
    __syncthreads();
    if (tid < 32) {
        s2 = (tid < 8) ? sh[tid] : 0.f;
#pragma unroll
        for (int o = 4; o; o >>= 1) s2 += __shfl_xor_sync(0xffffffffu, s2, o);
        if (tid == 0) sh[0] = s2;
    }
    __syncthreads();
    const float scale = rsqrtf(sh[0] * (1.f / DI) + 1e-5f);
#pragma unroll
    for (int u = 0; u < 2; u++) {
        const int j = tid * 4 + u * 1024;
        const float4 wv = *(const float4*)(rw + j);
        const float o0 = vals[u*4+0] * scale * wv.x;
        const float o1 = vals[u*4+1] * scale * wv.y;
        const float o2 = vals[u*4+2] * scale * wv.z;
        const float o3 = vals[u*4+3] * scale * wv.w;
        __nv_bfloat16 h0,h1,h2,h3,l0,l1,l2,l3;
        split_bf(o0,h0,l0); split_bf(o1,h1,l1); split_bf(o2,h2,l2); split_bf(o3,h3,l3);
        __nv_bfloat162 p;
        __nv_bfloat162* hp = (__nv_bfloat162*)(g_yhi + (size_t)row * DI + j);
        __nv_bfloat162* lp = (__nv_bfloat162*)(g_ylo + (size_t)row * DI + j);
        p.x=h0; p.y=h1; hp[0]=p;  p.x=h2; p.y=h3; hp[1]=p;
        p.x=l0; p.y=l1; lp[0]=p;  p.x=l2; p.y=l3; lp[1]=p;
    }
}

// ---------------- host launch ----------------
extern "C" void kernel_launch(void* const* d_in, const int* in_sizes, int n_in,
                              void* d_out, int out_size)
{
    const float* x       = (const float*)d_in[0];
    const float* ln_w    = (const float*)d_in[1];
    const float* ln_b    = (const float*)d_in[2];
    const float* in_proj = (const float*)d_in[3];
    const float* conv_w  = (const float*)d_in[4];
    const float* conv_b  = (const float*)d_in[5];
    const float* dt_bias = (const float*)d_in[6];
    const float* A_log   = (const float*)d_in[7];
    const float* Dvec    = (const float*)d_in[8];
    const float* rms_w   = (const float*)d_in[9];
    const float* out_w   = (const float*)d_in[10];
    float* out = (float*)d_out;

    float *p_h, *p_zx;
    __nv_bfloat16 *p_xhi, *p_xlo, *p_yhi, *p_ylo, *p_whi, *p_wlo;
    cudaGetSymbolAddress((void**)&p_h,   g_h);
    cudaGetSymbolAddress((void**)&p_zx,  g_zx);
    cudaGetSymbolAddress((void**)&p_xhi, g_xhi);
    cudaGetSymbolAddress((void**)&p_xlo, g_xlo);
    cudaGetSymbolAddress((void**)&p_yhi, g_yhi);
    cudaGetSymbolAddress((void**)&p_ylo, g_ylo);
    cudaGetSymbolAddress((void**)&p_whi, g_whi);
    cudaGetSymbolAddress((void**)&p_wlo, g_wlo);

    cudaFuncSetAttribute(gemm_mma, cudaFuncAttributeMaxDynamicSharedMemorySize, GEMM_SMEM);

    for (int i = 0; i < 2; i++) {
        const float* hin  = (i == 0) ? x   : p_h;
        float*       hout = (i == 0) ? p_h : out;

        ln_kernel<<<M_ROWS, 256>>>(hin, ln_w + i * DM, ln_b + i * DM, p_xhi, p_xlo);

        cvt_hilo<<<(DIP * DM / 4) / 256, 256>>>(in_proj + (size_t)i * DIP * DM, p_whi, p_wlo);

        gemm_mma<<<dim3((DIP + 127) / 128, M_ROWS / 128), 256, GEMM_SMEM>>>(
            p_xhi, p_xlo, p_whi, p_wlo, nullptr, p_zx, DIP, DM);

        dt_kernel<<<(M_ROWS * NH) / 256, 256>>>(dt_bias + i * NH, A_log + i * NH);

        conv_kernel<<<(M_ROWS * CDIM + 255) / 256, 256>>>(
            conv_w + (size_t)i * CDIM * 4, conv_b + (size_t)i * CDIM);

        scan_kernel<<<BATCH * NH, 256>>>(Dvec + i * NH);

        gaterms_kernel<<<M_ROWS, 256>>>(rms_w + (size_t)i * DI);

        cvt_hilo<<<(DM * DI / 4) / 256, 256>>>(out_w + (size_t)i * DM * DI, p_whi, p_wlo);

        gemm_mma<<<dim3(DM / 128, M_ROWS / 128), 256, GEMM_SMEM>>>(
            p_yhi, p_ylo, p_whi, p_wlo, hin, hout, DM, DI);
    }
}

// round 8
// speedup vs baseline: 1.9588x; 1.3646x over previous
#include <cuda_runtime.h>
#include <cuda_bf16.h>
#include <math.h>
#include <stdint.h>

#define BATCH 2
#define SEQ   4096
#define DM    1024
#define DIP   4256
#define DI    2048
#define CDIM  2176
#define NH    32
#define HD    64
#define NSTATE 64
#define M_ROWS (BATCH*SEQ)   /* 8192 */

// ---------------- scratch (device globals; no allocations allowed) ----------------
__device__ float g_zx[(size_t)M_ROWS * DIP];
__device__ float g_conv[(size_t)M_ROWS * CDIM];
__device__ float g_dt[(size_t)M_ROWS * NH];
__device__ float g_dA[(size_t)M_ROWS * NH];
__device__ float g_y[(size_t)M_ROWS * DI];
__device__ float g_y2[(size_t)M_ROWS * DI];
__device__ float g_h[(size_t)M_ROWS * DM];
__device__ __nv_bfloat16 g_xhi[(size_t)M_ROWS * DM];
__device__ __nv_bfloat16 g_xlo[(size_t)M_ROWS * DM];
__device__ __nv_bfloat16 g_yhi[(size_t)M_ROWS * DI];
__device__ __nv_bfloat16 g_ylo[(size_t)M_ROWS * DI];
__device__ __nv_bfloat16 g_whi[(size_t)DIP * DM];
__device__ __nv_bfloat16 g_wlo[(size_t)DIP * DM];

// ---------------- baseline-ISA PTX helpers ----------------
__device__ __forceinline__ uint32_t smem_u32_of(const void* p) {
    uint32_t a;
    asm("{ .reg .u64 t; cvta.to.shared.u64 t, %1; cvt.u32.u64 %0, t; }" : "=r"(a) : "l"(p));
    return a;
}
__device__ __forceinline__ void cp16(uint32_t dst, const void* src) {
    asm volatile("cp.async.cg.shared.global [%0], [%1], 16;" :: "r"(dst), "l"(src));
}
__device__ __forceinline__ void cp_commit() {
    asm volatile("cp.async.commit_group;" ::: "memory");
}
template<int N> __device__ __forceinline__ void cp_wait() {
    asm volatile("cp.async.wait_group %0;" :: "n"(N) : "memory");
}
__device__ __forceinline__ void ldsm_x4(uint32_t* r, uint32_t addr) {
    asm volatile("ldmatrix.sync.aligned.m8n8.x4.shared.b16 {%0,%1,%2,%3}, [%4];"
                 : "=r"(r[0]), "=r"(r[1]), "=r"(r[2]), "=r"(r[3]) : "r"(addr));
}
__device__ __forceinline__ void mma16816(float* d, const uint32_t* a, uint32_t b0, uint32_t b1) {
    asm volatile("mma.sync.aligned.m16n8k16.row.col.f32.bf16.bf16.f32 "
                 "{%0,%1,%2,%3}, {%4,%5,%6,%7}, {%8,%9}, {%0,%1,%2,%3};"
                 : "+f"(d[0]), "+f"(d[1]), "+f"(d[2]), "+f"(d[3])
                 : "r"(a[0]), "r"(a[1]), "r"(a[2]), "r"(a[3]), "r"(b0), "r"(b1));
}
__device__ __forceinline__ void split_bf(float v, __nv_bfloat16& h, __nv_bfloat16& l) {
    h = __float2bfloat16(v);
    l = __float2bfloat16(v - __bfloat162float(h));
}

// ---------------- weight fp32 -> (hi, lo) bf16 ----------------
__global__ void cvt_hilo(const float* __restrict__ s, __nv_bfloat16* __restrict__ hi,
                         __nv_bfloat16* __restrict__ lo)
{
    const size_t idx = (size_t)blockIdx.x * blockDim.x + threadIdx.x;
    const float4 v = ((const float4*)s)[idx];
    __nv_bfloat16 h0,h1,h2,h3,l0,l1,l2,l3;
    split_bf(v.x,h0,l0); split_bf(v.y,h1,l1); split_bf(v.z,h2,l2); split_bf(v.w,h3,l3);
    __nv_bfloat162 a,b;
    a.x=h0; a.y=h1; b.x=h2; b.y=h3;
    ((__nv_bfloat162*)hi)[idx*2]=a; ((__nv_bfloat162*)hi)[idx*2+1]=b;
    a.x=l0; a.y=l1; b.x=l2; b.y=l3;
    ((__nv_bfloat162*)lo)[idx*2]=a; ((__nv_bfloat162*)lo)[idx*2+1]=b;
}

// ---------------- HMMA bf16-split GEMM v2 ----------------
// C[M,Nn] = A[M,K]*W[Nn,K]^T (+Res). 3-term compensated bf16.
// CTA tile 256x128, 8 warps (4x2), warp tile 64x64, BK=32, 2-stage cp.async.
// SMEM rows 64B data + pad to 80B stride (conflict-free ldmatrix).
#define ROWB   80
#define OFF_AH 0
#define OFF_AL (256 * ROWB)               /* 20480 */
#define OFF_BH (2 * 256 * ROWB)           /* 40960 */
#define OFF_BL (OFF_BH + 128 * ROWB)      /* 51200 */
#define STAGE  (OFF_BL + 128 * ROWB)      /* 61440 */
#define GEMM_SMEM (2 * STAGE)             /* 122880 */

__global__ __launch_bounds__(256, 1)
void gemm_mma(const __nv_bfloat16* __restrict__ Ahi, const __nv_bfloat16* __restrict__ Alo,
              const __nv_bfloat16* __restrict__ Whi, const __nv_bfloat16* __restrict__ Wlo,
              const float* __restrict__ Res, float* __restrict__ C,
              int Nn, int K)
{
    extern __shared__ char smem[];
    const uint32_t sb = smem_u32_of(smem);
    const int tid  = threadIdx.x;
    const int wid  = tid >> 5;
    const int lane = tid & 31;
    const int bm = blockIdx.y * 256;
    const int bn = blockIdx.x * 128;
    const int wm = wid >> 1;           // 0..3 -> 64-row band
    const int wn = wid & 1;            // 0..1 -> 64-col band
    const int NC = K >> 5;

    float acc[4][8][4];
#pragma unroll
    for (int i = 0; i < 4; i++)
#pragma unroll
        for (int j = 0; j < 8; j++)
#pragma unroll
            for (int q = 0; q < 4; q++) acc[i][j][q] = 0.f;

    // global->smem mapping
    const int ra = tid;                // A row 0..255, all 4 chunks
    const int rb = tid >> 1;           // B row 0..127
    const int lc = (tid & 1) * 2;      // B chunk pair
    int brow = bn + rb; if (brow >= Nn) brow = Nn - 1;
    const __nv_bfloat16* pah = Ahi + (size_t)(bm + ra) * K;
    const __nv_bfloat16* pal = Alo + (size_t)(bm + ra) * K;
    const __nv_bfloat16* pbh = Whi + (size_t)brow * K;
    const __nv_bfloat16* pbl = Wlo + (size_t)brow * K;

#define LOAD_CHUNK(c) do {                                            \
    const uint32_t s0 = sb + ((c) & 1) * STAGE;                       \
    const int kof = (c) * 32;                                         \
    const uint32_t sa = s0 + ra * ROWB;                               \
    _Pragma("unroll")                                                 \
    for (int q = 0; q < 4; q++) {                                     \
        cp16(sa + OFF_AH + q * 16, pah + kof + q * 8);                \
        cp16(sa + OFF_AL + q * 16, pal + kof + q * 8);                \
    }                                                                 \
    const uint32_t sbr = s0 + rb * ROWB;                              \
    _Pragma("unroll")                                                 \
    for (int q = 0; q < 2; q++) {                                     \
        const int ch = lc + q;                                        \
        cp16(sbr + OFF_BH + ch * 16, pbh + kof + ch * 8);             \
        cp16(sbr + OFF_BL + ch * 16, pbl + kof + ch * 8);             \
    }                                                                 \
    cp_commit();                                                      \
} while (0)

    LOAD_CHUNK(0);
    if (NC > 1) LOAD_CHUNK(1);

    const int a_rb  = wm * 64 + (lane & 15);
    const int a_chk = (lane >> 4) * 16;
    const int b_rb  = wn * 64 + ((lane >> 4) << 3) + (lane & 7);
    const int b_chk = ((lane >> 3) & 1) * 16;

    for (int c = 0; c < NC; c++) {
        if (c + 1 < NC) cp_wait<1>(); else cp_wait<0>();
        __syncthreads();
        const uint32_t sbuf = sb + (c & 1) * STAGE;

#pragma unroll
        for (int ks = 0; ks < 2; ks++) {
            uint32_t ah[4][4], al[4][4];
#pragma unroll
            for (int im = 0; im < 4; im++) {
                const uint32_t addr = sbuf + (a_rb + im * 16) * ROWB + ks * 32 + a_chk;
                ldsm_x4(ah[im], addr + OFF_AH);
                ldsm_x4(al[im], addr + OFF_AL);
            }
#pragma unroll
            for (int g = 0; g < 4; g++) {
                uint32_t bh[4], bl[4];
                const uint32_t addr = sbuf + (b_rb + g * 16) * ROWB + ks * 32 + b_chk;
                ldsm_x4(bh, addr + OFF_BH);
                ldsm_x4(bl, addr + OFF_BL);
#pragma unroll
                for (int im = 0; im < 4; im++)
#pragma unroll
                    for (int hf = 0; hf < 2; hf++) {
                        float* d = acc[im][g * 2 + hf];
                        mma16816(d, ah[im], bh[hf*2], bh[hf*2+1]);
                        mma16816(d, ah[im], bl[hf*2], bl[hf*2+1]);
                        mma16816(d, al[im], bh[hf*2], bh[hf*2+1]);
                    }
            }
        }
        __syncthreads();
        if (c + 2 < NC) LOAD_CHUNK(c + 2);
    }
#undef LOAD_CHUNK

    // epilogue
#pragma unroll
    for (int im = 0; im < 4; im++) {
        const int r0 = bm + wm * 64 + im * 16 + (lane >> 2);
#pragma unroll
        for (int j = 0; j < 8; j++) {
            const int n0 = bn + wn * 64 + j * 8;
            if (n0 < Nn) {
                const int cc = n0 + (lane & 3) * 2;
                float2 v0 = make_float2(acc[im][j][0], acc[im][j][1]);
                float2 v1 = make_float2(acc[im][j][2], acc[im][j][3]);
                if (Res) {
                    const float2 r0v = *(const float2*)&Res[(size_t)r0 * Nn + cc];
                    const float2 r1v = *(const float2*)&Res[(size_t)(r0 + 8) * Nn + cc];
                    v0.x += r0v.x; v0.y += r0v.y;
                    v1.x += r1v.x; v1.y += r1v.y;
                }
                *(float2*)&C[(size_t)r0 * Nn + cc] = v0;
                *(float2*)&C[(size_t)(r0 + 8) * Nn + cc] = v1;
            }
        }
    }
}

// ---------------- LayerNorm -> bf16 hi/lo ----------------
__global__ void ln_kernel(const float* __restrict__ x, const float* __restrict__ w,
                          const float* __restrict__ b,
                          __nv_bfloat16* __restrict__ ohi, __nv_bfloat16* __restrict__ olo)
{
    __shared__ float sh1[8], sh2[8];
    const int row = blockIdx.x;
    const int tid = threadIdx.x;
    const float4 v = ((const float4*)(x + (size_t)row * DM))[tid];
    float s1 = v.x + v.y + v.z + v.w;
    float s2 = v.x*v.x + v.y*v.y + v.z*v.z + v.w*v.w;
#pragma unroll
    for (int o = 16; o; o >>= 1) {
        s1 += __shfl_xor_sync(0xffffffffu, s1, o);
        s2 += __shfl_xor_sync(0xffffffffu, s2, o);
    }
    if ((tid & 31) == 0) { sh1[tid >> 5] = s1; sh2[tid >> 5] = s2; }
    __syncthreads();
    if (tid < 32) {
        s1 = (tid < 8) ? sh1[tid] : 0.f;
        s2 = (tid < 8) ? sh2[tid] : 0.f;
#pragma unroll
        for (int o = 4; o; o >>= 1) {
            s1 += __shfl_xor_sync(0xffffffffu, s1, o);
            s2 += __shfl_xor_sync(0xffffffffu, s2, o);
        }
        if (tid == 0) { sh1[0] = s1; sh2[0] = s2; }
    }
    __syncthreads();
    const float mean = sh1[0] * (1.f / DM);
    const float var  = sh2[0] * (1.f / DM) - mean * mean;
    const float rstd = rsqrtf(var + 1e-5f);
    const float4 wv = ((const float4*)w)[tid];
    const float4 bv = ((const float4*)b)[tid];
    float o0 = (v.x - mean) * rstd * wv.x + bv.x;
    float o1 = (v.y - mean) * rstd * wv.y + bv.y;
    float o2 = (v.z - mean) * rstd * wv.z + bv.z;
    float o3 = (v.w - mean) * rstd * wv.w + bv.w;
    __nv_bfloat16 h0,h1,h2,h3,l0,l1,l2,l3;
    split_bf(o0,h0,l0); split_bf(o1,h1,l1); split_bf(o2,h2,l2); split_bf(o3,h3,l3);
    __nv_bfloat162 p;
    __nv_bfloat162* hp = (__nv_bfloat162*)(ohi + (size_t)row * DM) + tid * 2;
    __nv_bfloat162* lp = (__nv_bfloat162*)(olo + (size_t)row * DM) + tid * 2;
    p.x=h0; p.y=h1; hp[0]=p;  p.x=h2; p.y=h3; hp[1]=p;
    p.x=l0; p.y=l1; lp[0]=p;  p.x=l2; p.y=l3; lp[1]=p;
}

// ---------------- dt/softplus/dA ----------------
__global__ void dt_kernel(const float* __restrict__ dt_bias, const float* __restrict__ A_log)
{
    const int idx = blockIdx.x * blockDim.x + threadIdx.x;
    const int h = idx & (NH - 1);
    const int row = idx >> 5;
    const float raw = g_zx[(size_t)row * DIP + (DI + CDIM) + h] + dt_bias[h];
    const float dt = (raw > 20.f) ? raw : log1pf(expf(raw));
    const float A = -expf(A_log[h]);
    g_dt[idx] = dt;
    g_dA[idx] = expf(dt * A);
}

// ---------------- causal depthwise conv (d=4) + bias + SiLU ----------------
__global__ void conv_kernel(const float* __restrict__ cw, const float* __restrict__ cb)
{
    const int idx = blockIdx.x * blockDim.x + threadIdx.x;
    if (idx >= M_ROWS * CDIM) return;
    const int c = idx % CDIM;
    const int row = idx / CDIM;
    const int l = row & (SEQ - 1);
    const float w0 = cw[c*4+0], w1 = cw[c*4+1], w2 = cw[c*4+2], w3 = cw[c*4+3];
    float acc = cb[c];
    const size_t base = (size_t)row * DIP + DI + c;
    acc += g_zx[base] * w3;
    if (l >= 1) acc += g_zx[base - (size_t)DIP]     * w2;
    if (l >= 2) acc += g_zx[base - 2*(size_t)DIP]   * w1;
    if (l >= 3) acc += g_zx[base - 3*(size_t)DIP]   * w0;
    g_conv[idx] = acc * (1.f / (1.f + expf(-acc)));
}

// ---------------- selective scan, split over state-dim halves ----------------
// grid = 128: bh = blockIdx.x & 63, half = blockIdx.x >> 6.
// thread p = tid>>2 (head row), g = tid&3 owns 8 state cols of the 32-col half.
__global__ __launch_bounds__(256, 1)
void scan_kernel(const float* __restrict__ Dp)
{
    const int bh   = blockIdx.x & 63;
    const int half = blockIdx.x >> 6;
    const int b = bh >> 5, h = bh & 31;
    const int tid = threadIdx.x;
    const int p = tid >> 2, g = tid & 3, nb = g * 8;

    __shared__ float sX[16][64], sB[16][32], sC[16][32], sY[16][64];
    __shared__ float sdt[16], sda[16];

    float st[8];
#pragma unroll
    for (int i = 0; i < 8; i++) st[i] = 0.f;

    const float Dh = Dp[h];
    const size_t rowbase = (size_t)b * SEQ;
    const int boff = DI + half * 32;
    const int coff = DI + NSTATE + half * 32;
    float* yout = half ? g_y2 : g_y;

    for (int l0 = 0; l0 < SEQ; l0 += 16) {
#pragma unroll
        for (int i = tid; i < 16 * 64; i += 256) {
            const int t = i >> 6, j = i & 63;
            sX[t][j] = g_conv[(rowbase + l0 + t) * (size_t)CDIM + h * 64 + j];
        }
#pragma unroll
        for (int i = tid; i < 16 * 32; i += 256) {
            const int t = i >> 5, j = i & 31;
            const size_t r = (rowbase + l0 + t) * (size_t)CDIM;
            sB[t][j] = g_conv[r + boff + j];
            sC[t][j] = g_conv[r + coff + j];
        }
        if (tid < 16) {
            const size_t r = rowbase + l0 + tid;
            sdt[tid] = g_dt[r * NH + h];
            sda[tid] = g_dA[r * NH + h];
        }
        __syncthreads();

#pragma unroll
        for (int t = 0; t < 16; t++) {
            const float xv  = sX[t][p];
            const float dtx = sdt[t] * xv;
            const float dav = sda[t];
            float acc = 0.f;
            const float4* Bv = (const float4*)&sB[t][nb];
            const float4* Cv = (const float4*)&sC[t][nb];
#pragma unroll
            for (int q = 0; q < 2; q++) {
                const float4 bq = Bv[q];
                const float4 cq = Cv[q];
                st[4*q+0] = dav * st[4*q+0] + dtx * bq.x; acc = fmaf(st[4*q+0], cq.x, acc);
                st[4*q+1] = dav * st[4*q+1] + dtx * bq.y; acc = fmaf(st[4*q+1], cq.y, acc);
                st[4*q+2] = dav * st[4*q+2] + dtx * bq.z; acc = fmaf(st[4*q+2], cq.z, acc);
                st[4*q+3] = dav * st[4*q+3] + dtx * bq.w; acc = fmaf(st[4*q+3], cq.w, acc);
            }
            acc += __shfl_xor_sync(0xffffffffu, acc, 1);
            acc += __shfl_xor_sync(0xffffffffu, acc, 2);
            if (g == 0) sY[t][p] = acc;
        }
        __syncthreads();

#pragma unroll
        for (int i = tid; i < 16 * 64; i += 256) {
            const int t = i >> 6, j = i & 63;
            const float skip = half ? 0.f : Dh * sX[t][j];
            yout[(rowbase + l0 + t) * (size_t)DI + h * 64 + j] = sY[t][j] + skip;
        }
        __syncthreads();
    }
}

// ---------------- gate (silu(z)) + RMSNorm -> bf16 hi/lo ----------------
__global__ void gaterms_kernel(const float* __restrict__ rw)
{
    __shared__ float sh[8];
    const int row = blockIdx.x;
    const int tid = threadIdx.x;
    const float* yr = g_y  + (size_t)row * DI;
    const float* y2 = g_y2 + (size_t)row * DI;
    const float* zr = g_zx + (size_t)row * DIP;
    float vals[8];
    float s2 = 0.f;
#pragma unroll
    for (int u = 0; u < 2; u++) {
        const int j = tid * 4 + u * 1024;
        const float4 yv = *(const float4*)(yr + j);
        const float4 y2v = *(const float4*)(y2 + j);
        const float4 zv = *(const float4*)(zr + j);
        const float y0 = yv.x + y2v.x, y1 = yv.y + y2v.y;
        const float y2s = yv.z + y2v.z, y3 = yv.w + y2v.w;
        const float g0 = y0 * (zv.x / (1.f + expf(-zv.x)));
        const float g1 = y1 * (zv.y / (1.f + expf(-zv.y)));
        const float g2 = y2s * (zv.z / (1.f + expf(-zv.z)));
        const float g3 = y3 * (zv.w / (1.f + expf(-zv.w)));
        vals[u*4+0] = g0; vals[u*4+1] = g1; vals[u*4+2] = g2; vals[u*4+3] = g3;
        s2 += g0*g0 + g1*g1 + g2*g2 + g3*g3;
    }
#pragma unroll
    for (int o = 16; o; o >>= 1) s2 += __shfl_xor_sync(0xffffffffu, s2, o);
    if ((tid & 31) == 0) sh[tid >> 5] = s2;
    __syncthreads();
    if (tid < 32) {
        s2 = (tid < 8) ? sh[tid] : 0.f;
#pragma unroll
        for (int o = 4; o; o >>= 1) s2 += __shfl_xor_sync(0xffffffffu, s2, o);
        if (tid == 0) sh[0] = s2;
    }
    __syncthreads();
    const float scale = rsqrtf(sh[0] * (1.f / DI) + 1e-5f);
#pragma unroll
    for (int u = 0; u < 2; u++) {
        const int j = tid * 4 + u * 1024;
        const float4 wv = *(const float4*)(rw + j);
        const float o0 = vals[u*4+0] * scale * wv.x;
        const float o1 = vals[u*4+1] * scale * wv.y;
        const float o2 = vals[u*4+2] * scale * wv.z;
        const float o3 = vals[u*4+3] * scale * wv.w;
        __nv_bfloat16 h0,h1,h2,h3,l0,l1,l2,l3;
        split_bf(o0,h0,l0); split_bf(o1,h1,l1); split_bf(o2,h2,l2); split_bf(o3,h3,l3);
        __nv_bfloat162 p;
        __nv_bfloat162* hp = (__nv_bfloat162*)(g_yhi + (size_t)row * DI + j);
        __nv_bfloat162* lp = (__nv_bfloat162*)(g_ylo + (size_t)row * DI + j);
        p.x=h0; p.y=h1; hp[0]=p;  p.x=h2; p.y=h3; hp[1]=p;
        p.x=l0; p.y=l1; lp[0]=p;  p.x=l2; p.y=l3; lp[1]=p;
    }
}

// ---------------- host launch ----------------
extern "C" void kernel_launch(void* const* d_in, const int* in_sizes, int n_in,
                              void* d_out, int out_size)
{
    const float* x       = (const float*)d_in[0];
    const float* ln_w    = (const float*)d_in[1];
    const float* ln_b    = (const float*)d_in[2];
    const float* in_proj = (const float*)d_in[3];
    const float* conv_w  = (const float*)d_in[4];
    const float* conv_b  = (const float*)d_in[5];
    const float* dt_bias = (const float*)d_in[6];
    const float* A_log   = (const float*)d_in[7];
    const float* Dvec    = (const float*)d_in[8];
    const float* rms_w   = (const float*)d_in[9];
    const float* out_w   = (const float*)d_in[10];
    float* out = (float*)d_out;

    float *p_h, *p_zx;
    __nv_bfloat16 *p_xhi, *p_xlo, *p_yhi, *p_ylo, *p_whi, *p_wlo;
    cudaGetSymbolAddress((void**)&p_h,   g_h);
    cudaGetSymbolAddress((void**)&p_zx,  g_zx);
    cudaGetSymbolAddress((void**)&p_xhi, g_xhi);
    cudaGetSymbolAddress((void**)&p_xlo, g_xlo);
    cudaGetSymbolAddress((void**)&p_yhi, g_yhi);
    cudaGetSymbolAddress((void**)&p_ylo, g_ylo);
    cudaGetSymbolAddress((void**)&p_whi, g_whi);
    cudaGetSymbolAddress((void**)&p_wlo, g_wlo);

    cudaFuncSetAttribute(gemm_mma, cudaFuncAttributeMaxDynamicSharedMemorySize, GEMM_SMEM);

    for (int i = 0; i < 2; i++) {
        const float* hin  = (i == 0) ? x   : p_h;
        float*       hout = (i == 0) ? p_h : out;

        ln_kernel<<<M_ROWS, 256>>>(hin, ln_w + i * DM, ln_b + i * DM, p_xhi, p_xlo);

        cvt_hilo<<<(DIP * DM / 4) / 256, 256>>>(in_proj + (size_t)i * DIP * DM, p_whi, p_wlo);

        gemm_mma<<<dim3((DIP + 127) / 128, M_ROWS / 256), 256, GEMM_SMEM>>>(
            p_xhi, p_xlo, p_whi, p_wlo, nullptr, p_zx, DIP, DM);

        dt_kernel<<<(M_ROWS * NH) / 256, 256>>>(dt_bias + i * NH, A_log + i * NH);

        conv_kernel<<<(M_ROWS * CDIM + 255) / 256, 256>>>(
            conv_w + (size_t)i * CDIM * 4, conv_b + (size_t)i * CDIM);

        scan_kernel<<<2 * BATCH * NH, 256>>>(Dvec + i * NH);

        gaterms_kernel<<<M_ROWS, 256>>>(rms_w + (size_t)i * DI);

        cvt_hilo<<<(DM * DI / 4) / 256, 256>>>(out_w + (size_t)i * DM * DI, p_whi, p_wlo);

        gemm_mma<<<dim3(DM / 128, M_ROWS / 256), 256, GEMM_SMEM>>>(
            p_yhi, p_ylo, p_whi, p_wlo, hin, hout, DM, DI);
    }
}